// round 8
// baseline (speedup 1.0000x reference)
#include <cuda_runtime.h>
#include <math_constants.h>

// RoiMaxPooling: x (256,56,56,256) f32 NHWC -> adaptive 7x7 max pool (8x8 bins)
// with the reference's transpose/reshape index scramble:
//   out_linear_row = w*(7*B) + h*B + b
//
// R8: FOUR independent bins (chains) per thread. R7 showed chain count is
// the live lever (1 chain: 121.0us, 2 chains: 119.8us) -- each extra chain
// gives the scheduler independent loads to issue while another chain sits
// at its vmax join. Same proven geometry: 256 thr, 2 CTAs/SM, 128-reg cap,
// classic launch, __ldcs/__stcs. 16 bins/block -> grid=784.

#define B_   256
#define HH   56
#define WW   56
#define CC   256
#define GH   7
#define GW   7

__device__ __forceinline__ float4 vmax4(float4 a, float4 b) {
    return make_float4(fmaxf(a.x, b.x), fmaxf(a.y, b.y),
                       fmaxf(a.z, b.z), fmaxf(a.w, b.w));
}

__global__ __launch_bounds__(256, 2)
void roi_maxpool_kernel(const float4* __restrict__ x, float4* __restrict__ out) {
    // Block covers 16 bins: 4 thread-groups of 64 threads, each group owns
    // 4 consecutive bins (four independent chains per thread).
    const int t    = threadIdx.x;
    const int grp  = t >> 6;                          // 0..3
    const int lane = t & 63;                          // channel-group 0..63
    const int bin0 = (blockIdx.x << 4) + (grp << 2);  // first of 4 bins

    const int C4  = CC / 4;        // 64 float4 per pixel
    const int ROW = WW * C4;       // float4 per H-row (3584)

    int base[4], orow[4];
    #pragma unroll
    for (int j = 0; j < 4; j++) {
        const int bin = bin0 + j;
        const int b  = bin / (GH * GW);
        const int hw = bin - b * (GH * GW);
        const int h  = hw / GW;
        const int w  = hw - h * GW;
        base[j] = ((b * HH + h * 8) * WW + w * 8) * C4 + lane;
        orow[j] = (w * (GH * B_) + h * B_ + b);
    }

    float4 acc[4];
    #pragma unroll
    for (int j = 0; j < 4; j++)
        acc[j] = make_float4(-CUDART_INF_F, -CUDART_INF_F,
                             -CUDART_INF_F, -CUDART_INF_F);

    #pragma unroll
    for (int i = 0; i < 8; i++) {
        #pragma unroll
        for (int j = 0; j < 4; j++) {
            const float4* rp = x + base[j] + i * ROW;
            float4 v0 = __ldcs(rp + 0 * C4);
            float4 v1 = __ldcs(rp + 1 * C4);
            float4 v2 = __ldcs(rp + 2 * C4);
            float4 v3 = __ldcs(rp + 3 * C4);
            float4 v4 = __ldcs(rp + 4 * C4);
            float4 v5 = __ldcs(rp + 5 * C4);
            float4 v6 = __ldcs(rp + 6 * C4);
            float4 v7 = __ldcs(rp + 7 * C4);
            float4 tj = vmax4(vmax4(vmax4(v0, v1), vmax4(v2, v3)),
                              vmax4(vmax4(v4, v5), vmax4(v6, v7)));
            acc[j] = vmax4(acc[j], tj);
        }
    }

    #pragma unroll
    for (int j = 0; j < 4; j++)
        __stcs(out + orow[j] * C4 + lane, acc[j]);
}

extern "C" void kernel_launch(void* const* d_in, const int* in_sizes, int n_in,
                              void* d_out, int out_size) {
    const float4* x = (const float4*)d_in[0];
    float4* out = (float4*)d_out;
    const int n_bins = B_ * GH * GW;          // 12544
    const int blocks = n_bins / 16;           // 784
    roi_maxpool_kernel<<<blocks, 256>>>(x, out);
}

// round 9
// speedup vs baseline: 1.0185x; 1.0185x over previous
#include <cuda_runtime.h>
#include <math_constants.h>

// RoiMaxPooling: x (256,56,56,256) f32 NHWC -> adaptive 7x7 max pool (8x8 bins)
// with the reference's transpose/reshape index scramble:
//   out_linear_row = w*(7*B) + h*B + b
//
// R9: R7's winning 2-independent-chain structure (1 chain: 121.0us,
// 2 chains: 119.8us, 4 chains: 123.4us -> 2 is the register-budget optimum),
// but the two bins per thread are now HALF THE TENSOR APART (bin, bin+6272:
// ~411MB) instead of adjacent: every warp drives both HBM halves / both L2
// dies simultaneously -> more DRAM bank-level parallelism per request set.
// Geometry unchanged: 256 thr, 2 CTAs/SM, grid 1568, __ldcs/__stcs.

#define B_   256
#define HH   56
#define WW   56
#define CC   256
#define GH   7
#define GW   7

#define NBINS      (B_ * GH * GW)   // 12544
#define HALF_BINS  (NBINS / 2)      // 6272

__device__ __forceinline__ float4 vmax4(float4 a, float4 b) {
    return make_float4(fmaxf(a.x, b.x), fmaxf(a.y, b.y),
                       fmaxf(a.z, b.z), fmaxf(a.w, b.w));
}

__global__ __launch_bounds__(256, 2)
void roi_maxpool_kernel(const float4* __restrict__ x, float4* __restrict__ out) {
    // 4 thread-groups of 64 threads; each group owns bin0 in [0, 6272) and
    // its distant partner bin0 + 6272.
    const int t    = threadIdx.x;
    const int grp  = t >> 6;                          // 0..3
    const int lane = t & 63;                          // channel-group 0..63
    const int bin0 = (blockIdx.x << 2) + grp;         // 0 .. 6271
    const int bin1 = bin0 + HALF_BINS;                // 6272 .. 12543

    const int C4  = CC / 4;        // 64 float4 per pixel
    const int ROW = WW * C4;       // float4 per H-row (3584)

    // bin0 coords
    const int b0  = bin0 / (GH * GW);
    const int hw0 = bin0 - b0 * (GH * GW);
    const int h0  = hw0 / GW;
    const int w0  = hw0 - h0 * GW;
    // bin1 coords
    const int b1  = bin1 / (GH * GW);
    const int hw1 = bin1 - b1 * (GH * GW);
    const int h1  = hw1 / GW;
    const int w1  = hw1 - h1 * GW;

    const int base0 = ((b0 * HH + h0 * 8) * WW + w0 * 8) * C4 + lane;
    const int base1 = ((b1 * HH + h1 * 8) * WW + w1 * 8) * C4 + lane;

    float4 accA = make_float4(-CUDART_INF_F, -CUDART_INF_F,
                              -CUDART_INF_F, -CUDART_INF_F);
    float4 accB = accA;

    #pragma unroll
    for (int i = 0; i < 8; i++) {
        const float4* ra = x + base0 + i * ROW;
        const float4* rb = x + base1 + i * ROW;
        // chain A: 8 streaming LDG.128 (low half of tensor)
        float4 a0 = __ldcs(ra + 0 * C4);
        float4 a1 = __ldcs(ra + 1 * C4);
        float4 a2 = __ldcs(ra + 2 * C4);
        float4 a3 = __ldcs(ra + 3 * C4);
        float4 a4 = __ldcs(ra + 4 * C4);
        float4 a5 = __ldcs(ra + 5 * C4);
        float4 a6 = __ldcs(ra + 6 * C4);
        float4 a7 = __ldcs(ra + 7 * C4);
        // chain B: 8 streaming LDG.128 (high half of tensor, independent)
        float4 c0 = __ldcs(rb + 0 * C4);
        float4 c1 = __ldcs(rb + 1 * C4);
        float4 c2 = __ldcs(rb + 2 * C4);
        float4 c3 = __ldcs(rb + 3 * C4);
        float4 c4 = __ldcs(rb + 4 * C4);
        float4 c5 = __ldcs(rb + 5 * C4);
        float4 c6 = __ldcs(rb + 6 * C4);
        float4 c7 = __ldcs(rb + 7 * C4);

        float4 ta = vmax4(vmax4(vmax4(a0, a1), vmax4(a2, a3)),
                          vmax4(vmax4(a4, a5), vmax4(a6, a7)));
        float4 tb = vmax4(vmax4(vmax4(c0, c1), vmax4(c2, c3)),
                          vmax4(vmax4(c4, c5), vmax4(c6, c7)));
        accA = vmax4(accA, ta);
        accB = vmax4(accB, tb);
    }

    // Scrambled destinations: linear row = w*(GH*B) + h*B + b
    const int orow0 = (w0 * (GH * B_) + h0 * B_ + b0);
    const int orow1 = (w1 * (GH * B_) + h1 * B_ + b1);
    __stcs(out + orow0 * C4 + lane, accA);
    __stcs(out + orow1 * C4 + lane, accB);
}

extern "C" void kernel_launch(void* const* d_in, const int* in_sizes, int n_in,
                              void* d_out, int out_size) {
    const float4* x = (const float4*)d_in[0];
    float4* out = (float4*)d_out;
    const int blocks = HALF_BINS / 4;         // 1568
    roi_maxpool_kernel<<<blocks, 256>>>(x, out);
}